// round 9
// baseline (speedup 1.0000x reference)
#include <cuda_runtime.h>
#include <mma.h>
#include <math.h>
#include <stdint.h>

using namespace nvcuda;

#define TT 256      // timesteps
#define BB 256      // batch
#define DD 1024     // hidden dim
#define WS 2048     // W row stride (W is (D, 2D) row-major)

// ===========================================================================
// mbarrier + bulk-copy helpers (UBLKCP path: no per-16B LSU issue cost)
// ===========================================================================
__device__ __forceinline__ void mbar_init(uint32_t mbar, unsigned count) {
    asm volatile("mbarrier.init.shared.b64 [%0], %1;" :: "r"(mbar), "r"(count) : "memory");
}
__device__ __forceinline__ void mbar_expect_tx(uint32_t mbar, unsigned bytes) {
    asm volatile("mbarrier.arrive.expect_tx.shared.b64 _, [%0], %1;"
                 :: "r"(mbar), "r"(bytes) : "memory");
}
__device__ __forceinline__ void mbar_wait(uint32_t mbar, unsigned parity) {
    asm volatile("{\n\t.reg .pred P;\n\tWL%=:\n\t"
                 "mbarrier.try_wait.parity.shared.b64 P, [%0], %1;\n\t"
                 "@!P bra WL%=;\n\t}"
                 :: "r"(mbar), "r"(parity) : "memory");
}
__device__ __forceinline__ void bulk_g2s(uint32_t dst, const void* src,
                                         unsigned bytes, uint32_t mbar) {
    asm volatile("cp.async.bulk.shared::cta.global.mbarrier::complete_tx::bytes "
                 "[%0], [%1], %2, [%3];"
                 :: "r"(dst), "l"(src), "r"(bytes), "r"(mbar) : "memory");
}

// ===========================================================================
// Kernel 1: preactivations, tf32 wmma, 128x128 tile, bulk-copy loader.
//   out[(b*TT + t)*DD + d] = bias[d] + sum_k x[(t*BB+b)*DD + k] * W[d*WS + k]
// ===========================================================================
#define X_BM 128
#define X_BN 128
#define X_BK 32
#define X_LD 36                       // padded smem ldm (144B rows, 16B-mult)
#define X_TILE (X_BM * X_LD)          // 4608 floats
#define X_SMEM_FLOATS (4 * X_TILE)    // 18432 floats (73.7 KB)

__global__ void __launch_bounds__(256)
gemm_x_tf32(const float* __restrict__ x, const float* __restrict__ W,
            const float* __restrict__ bias, float* __restrict__ out)
{
    extern __shared__ float sm[];
    float* sA[2] = { sm,              sm + 2 * X_TILE };
    float* sB[2] = { sm + X_TILE,     sm + 3 * X_TILE };
    __shared__ __align__(8) unsigned long long mbX[2];

    const int r0   = blockIdx.y * X_BM;   // row tile in (t*BB + b) space
    const int d0   = blockIdx.x * X_BN;
    const int tid  = threadIdx.x;
    const int wid  = tid >> 5;
    const int lane = tid & 31;
    const int warpM = wid & 3;            // 4 x 32 rows
    const int warpN = wid >> 2;           // 2 x 64 cols

    const uint32_t mb[2] = {
        (uint32_t)__cvta_generic_to_shared(&mbX[0]),
        (uint32_t)__cvta_generic_to_shared(&mbX[1])
    };
    const uint32_t sAu[2] = {
        (uint32_t)__cvta_generic_to_shared(sA[0]),
        (uint32_t)__cvta_generic_to_shared(sA[1])
    };
    const uint32_t sBu[2] = {
        (uint32_t)__cvta_generic_to_shared(sB[0]),
        (uint32_t)__cvta_generic_to_shared(sB[1])
    };

    if (tid == 0) { mbar_init(mb[0], 1); mbar_init(mb[1], 1); }
    __syncthreads();

    // fill one chunk (A 128x32 + B 128x32): 256 bulk copies of 128B, warp 0 only
    auto fill = [&](int c, int buf) {
        if (wid == 0) {
            if (lane == 0) mbar_expect_tx(mb[buf], 2u * X_BM * 128u);  // 32768 B
            __syncwarp();
            #pragma unroll
            for (int j = 0; j < 4; ++j) {
                int row = lane + j * 32;
                bulk_g2s(sAu[buf] + (unsigned)(row * X_LD) * 4u,
                         &x[(size_t)(r0 + row) * DD + c * X_BK], 128u, mb[buf]);
                bulk_g2s(sBu[buf] + (unsigned)(row * X_LD) * 4u,
                         &W[(size_t)(d0 + row) * WS + c * X_BK], 128u, mb[buf]);
            }
        }
    };

    wmma::fragment<wmma::accumulator, 16, 16, 8, float> acc[2][4];
    #pragma unroll
    for (int mi = 0; mi < 2; ++mi)
        #pragma unroll
        for (int ni = 0; ni < 4; ++ni)
            wmma::fill_fragment(acc[mi][ni], 0.0f);

    fill(0, 0);
    fill(1, 1);

    unsigned ph[2] = {0, 0};
    const int NCH = DD / X_BK;            // 32 chunks
    for (int c = 0; c < NCH; ++c) {
        int buf = c & 1;
        mbar_wait(mb[buf], ph[buf]);
        ph[buf] ^= 1;

        #pragma unroll
        for (int kk = 0; kk < X_BK; kk += 8) {
            wmma::fragment<wmma::matrix_a, 16, 16, 8, wmma::precision::tf32, wmma::row_major> a[2];
            #pragma unroll
            for (int mi = 0; mi < 2; ++mi)
                wmma::load_matrix_sync(a[mi], &sA[buf][(warpM * 32 + mi * 16) * X_LD + kk], X_LD);
            #pragma unroll
            for (int ni = 0; ni < 4; ++ni) {
                wmma::fragment<wmma::matrix_b, 16, 16, 8, wmma::precision::tf32, wmma::col_major> b;
                wmma::load_matrix_sync(b, &sB[buf][(warpN * 64 + ni * 16) * X_LD + kk], X_LD);
                #pragma unroll
                for (int mi = 0; mi < 2; ++mi)
                    wmma::mma_sync(acc[mi][ni], a[mi], b, acc[mi][ni]);
            }
        }
        __syncthreads();                  // all reads of buf done
        if (c + 2 < NCH) fill(c + 2, buf);
    }

    // Stage C in smem (alias buffers: 16384 <= 18432 floats)
    float* sC = sm;
    __syncthreads();
    #pragma unroll
    for (int mi = 0; mi < 2; ++mi)
        #pragma unroll
        for (int ni = 0; ni < 4; ++ni)
            wmma::store_matrix_sync(&sC[(warpM * 32 + mi * 16) * X_BN + warpN * 64 + ni * 16],
                                    acc[mi][ni], X_BN, wmma::mem_row_major);
    __syncthreads();

    // Epilogue: +bias, scatter. Block spans 128 rows => t constant.
    const int t = r0 >> 8;
    const int bbase = r0 & 255;
    #pragma unroll
    for (int j = 0; j < 16; ++j) {
        int f   = tid + j * 256;          // 4096 float4
        int row = f >> 5;                 // 32 float4 per row
        int c4  = f & 31;
        float4 bv = *reinterpret_cast<const float4*>(&bias[d0 + c4 * 4]);
        const float* cp = &sC[row * X_BN + c4 * 4];
        float4 o;
        o.x = cp[0] + bv.x; o.y = cp[1] + bv.y; o.z = cp[2] + bv.z; o.w = cp[3] + bv.w;
        *reinterpret_cast<float4*>(
            &out[((size_t)((bbase + row) * TT + t)) * DD + d0 + c4 * 4]) = o;
    }
}

// ===========================================================================
// Kernel 2: persistent recurrence.
//   - 128 blocks x 512 threads; block tile = 64 batch x 32 d.
//   - Wh stripe (32x1024, RN->tf32) resident in smem for all 256 steps.
//   - h streamed via cp.async.bulk: 64 copies of 512B per chunk (warp 0),
//     mbarrier complete_tx. No LSU per-16B issue cost.
//   - 16 warps = 4(M) x 2(N) x 2(K-half); combine via smem C0/C1.
//   - 4 independent batch groups of 32 blocks; acq/rel barrier.
// ===========================================================================
#define RH_WLD 1028                     // Wh smem ldm (1024 + 4)
#define RH_ALD 132                      // h  smem ldm (128 + 4) -> 528B rows
#define RH_BM 64
#define RH_BN 32
#define RH_BK 128
#define RH_NCH (DD / RH_BK)             // 8 chunks
#define RH_GRPBLK 32                    // blocks per barrier group

#define RH_OFF_WH 0
#define RH_OFF_A0 (RH_BN * RH_WLD)                    // 32896
#define RH_OFF_A1 (RH_OFF_A0 + RH_BM * RH_ALD)       // 41344
#define RH_OFF_C0 (RH_OFF_A1 + RH_BM * RH_ALD)       // 49792
#define RH_OFF_C1 (RH_OFF_C0 + RH_BM * RH_BN)        // 51840
#define RH_SMEM_FLOATS (RH_OFF_C1 + RH_BM * RH_BN)   // 53888 floats = 210.5 KB

__device__ __align__(256) unsigned g_cnt[4 * 64];
__device__ __align__(256) unsigned g_phase[4 * 64];   // monotonic across replays

__device__ __forceinline__ unsigned bar_arrive_acqrel(unsigned* p) {
    unsigned old;
    asm volatile("atom.acq_rel.gpu.add.u32 %0,[%1],1;"
                 : "=r"(old) : "l"(p) : "memory");
    return old;
}
__device__ __forceinline__ void bar_reset_relaxed(unsigned* p) {
    asm volatile("st.relaxed.gpu.u32 [%0],0;" :: "l"(p) : "memory");
}
__device__ __forceinline__ void bar_release(unsigned* p) {
    asm volatile("red.release.gpu.add.u32 [%0],1;" :: "l"(p) : "memory");
}
__device__ __forceinline__ unsigned bar_poll_acquire(const unsigned* p) {
    unsigned v;
    asm volatile("ld.acquire.gpu.u32 %0,[%1];" : "=r"(v) : "l"(p) : "memory");
    return v;
}

__global__ void __launch_bounds__(512)
rnn_persistent(const float* __restrict__ W, float* __restrict__ out)
{
    extern __shared__ float sm[];
    float* sWh   = sm + RH_OFF_WH;
    float* sA[2] = { sm + RH_OFF_A0, sm + RH_OFF_A1 };
    float* sC[2] = { sm + RH_OFF_C0, sm + RH_OFF_C1 };
    __shared__ __align__(8) unsigned long long mbH[2];
    __shared__ unsigned s_base;

    const int tid  = threadIdx.x;
    const int wid  = tid >> 5;          // 16 warps
    const int lane = tid & 31;
    const int wM    = wid & 3;          // 4 x 16 rows = 64
    const int wN    = (wid >> 2) & 1;   // 2 x 16 cols = 32
    const int kHalf = wid >> 3;         // 2-way K split within each 128 chunk

    const int nT = blockIdx.x & 31;     // 32 d-stripes
    const int mT = blockIdx.x >> 5;     // 4 batch groups (barrier scope)
    const int d0 = nT * RH_BN;
    const int b0 = mT * RH_BM;

    unsigned* cntp   = &g_cnt[mT * 64];
    unsigned* phasep = &g_phase[mT * 64];

    const uint32_t mb[2] = {
        (uint32_t)__cvta_generic_to_shared(&mbH[0]),
        (uint32_t)__cvta_generic_to_shared(&mbH[1])
    };
    const uint32_t sAu[2] = {
        (uint32_t)__cvta_generic_to_shared(sA[0]),
        (uint32_t)__cvta_generic_to_shared(sA[1])
    };

    if (tid == 0) { mbar_init(mb[0], 1); mbar_init(mb[1], 1); }

    // --- Load Wh stripe once (RN-rounded to tf32): sWh[d][k], d=0..31 ---
    {
        const float* Wh = W + DD;
        #pragma unroll
        for (int j = 0; j < 16; ++j) {
            int f   = tid + j * 512;       // 8192 float4
            int row = f >> 8;              // 256 float4 per row
            int c4  = f & 255;
            float4 v = *reinterpret_cast<const float4*>(
                &Wh[(size_t)(d0 + row) * WS + c4 * 4]);
            float* p = &sWh[row * RH_WLD + c4 * 4];
            p[0] = wmma::__float_to_tf32(v.x);
            p[1] = wmma::__float_to_tf32(v.y);
            p[2] = wmma::__float_to_tf32(v.z);
            p[3] = wmma::__float_to_tf32(v.w);
        }
    }

    if (tid == 0) s_base = bar_poll_acquire(phasep);
    __syncthreads();
    const unsigned base = s_base;

    // fill one 64x128 h chunk: 64 bulk copies of 512B, warp 0 only
    auto fill_h = [&](int tprev, int c, int buf) {
        if (wid == 0) {
            if (lane == 0) mbar_expect_tx(mb[buf], RH_BM * 512u);   // 32768 B
            __syncwarp();
            bulk_g2s(sAu[buf] + (unsigned)(lane * RH_ALD) * 4u,
                     &out[((size_t)((b0 + lane) * TT + tprev)) * DD + c * RH_BK],
                     512u, mb[buf]);
            bulk_g2s(sAu[buf] + (unsigned)((lane + 32) * RH_ALD) * 4u,
                     &out[((size_t)((b0 + lane + 32) * TT + tprev)) * DD + c * RH_BK],
                     512u, mb[buf]);
        }
    };

    // epilogue thread map: 64x32 = 512 float4, 1 per thread
    const int erow = tid >> 3;             // 8 float4 per row
    const int ec4  = tid & 7;

    unsigned lph[2] = {0, 0};

    for (int t = 0; t < TT; ++t) {
        if (t == 0) {
            float* p = &out[((size_t)((b0 + erow) * TT + 0)) * DD + d0 + ec4 * 4];
            float4 v = *reinterpret_cast<const float4*>(p);
            v.x = tanhf(v.x); v.y = tanhf(v.y); v.z = tanhf(v.z); v.w = tanhf(v.w);
            *reinterpret_cast<float4*>(p) = v;
        } else {
            // prefetch this thread's preactivation (independent of h)
            float* eptr = &out[((size_t)((b0 + erow) * TT + t)) * DD + d0 + ec4 * 4];
            float4 pre = __ldcg(reinterpret_cast<const float4*>(eptr));

            wmma::fragment<wmma::accumulator, 16, 16, 8, float> acc[2];
            wmma::fill_fragment(acc[0], 0.0f);
            wmma::fill_fragment(acc[1], 0.0f);

            fill_h(t - 1, 0, 0);
            fill_h(t - 1, 1, 1);

            for (int c = 0; c < RH_NCH; ++c) {       // 8 chunks
                int buf = c & 1;
                mbar_wait(mb[buf], lph[buf]);
                lph[buf] ^= 1;

                const float* ap = &sA[buf][wM * 16 * RH_ALD + kHalf * 64];
                const float* bp = &sWh[(wN * 16) * RH_WLD + c * RH_BK + kHalf * 64];
                #pragma unroll
                for (int kk = 0; kk < 64; kk += 8) {
                    wmma::fragment<wmma::matrix_a, 16, 16, 8, wmma::precision::tf32, wmma::row_major> a;
                    wmma::fragment<wmma::matrix_b, 16, 16, 8, wmma::precision::tf32, wmma::col_major> b;
                    wmma::load_matrix_sync(a, ap + kk, RH_ALD);
                    wmma::load_matrix_sync(b, bp + kk, RH_WLD);
                    wmma::mma_sync(acc[(kk >> 3) & 1], a, b, acc[(kk >> 3) & 1]);
                }
                __syncthreads();                     // all reads of buf done
                if (c + 2 < RH_NCH) fill_h(t - 1, c + 2, buf);
            }

            // reduce 2 accs within warp, combine the 2 kHalf warps via smem
            #pragma unroll
            for (int e = 0; e < acc[0].num_elements; ++e)
                acc[0].x[e] += acc[1].x[e];
            wmma::store_matrix_sync(&sC[kHalf][(wM * 16) * RH_BN + wN * 16],
                                    acc[0], RH_BN, wmma::mem_row_major);
            __syncthreads();

            // epilogue: sC0 + sC1 + preact -> tanh -> store in place
            {
                const float* c0 = &sC[0][erow * RH_BN + ec4 * 4];
                const float* c1 = &sC[1][erow * RH_BN + ec4 * 4];
                float4 o;
                o.x = tanhf(pre.x + c0[0] + c1[0]);
                o.y = tanhf(pre.y + c0[1] + c1[1]);
                o.z = tanhf(pre.z + c0[2] + c1[2]);
                o.w = tanhf(pre.w + c0[3] + c1[3]);
                *reinterpret_cast<float4*>(eptr) = o;
            }
        }

        // group barrier (32 blocks sharing this batch group), skip after last
        if (t != TT - 1) {
            __syncthreads();
            if (tid == 0) {
                unsigned old = bar_arrive_acqrel(cntp);
                if (old == RH_GRPBLK - 1) {
                    bar_reset_relaxed(cntp);
                    bar_release(phasep);
                } else {
                    const unsigned target = base + (unsigned)(t + 1);
                    while ((int)(bar_poll_acquire(phasep) - target) < 0) { }
                }
            }
            __syncthreads();
        }
    }
}

// ===========================================================================
// Launch
// ===========================================================================
extern "C" void kernel_launch(void* const* d_in, const int* in_sizes, int n_in,
                              void* d_out, int out_size)
{
    const float* x    = (const float*)d_in[0];
    const float* W    = (const float*)d_in[1];
    const float* bias = (const float*)d_in[2];
    float* out = (float*)d_out;

    cudaFuncSetAttribute(gemm_x_tf32, cudaFuncAttributeMaxDynamicSharedMemorySize,
                         X_SMEM_FLOATS * sizeof(float));
    cudaFuncSetAttribute(rnn_persistent, cudaFuncAttributeMaxDynamicSharedMemorySize,
                         RH_SMEM_FLOATS * sizeof(float));

    dim3 g1(DD / X_BN, (TT * BB) / X_BM);   // (8, 512)
    gemm_x_tf32<<<g1, 256, X_SMEM_FLOATS * sizeof(float)>>>(x, W, bias, out);

    rnn_persistent<<<128, 512, RH_SMEM_FLOATS * sizeof(float)>>>(W, out);
}

// round 10
// speedup vs baseline: 4.8200x; 4.8200x over previous
#include <cuda_runtime.h>
#include <cuda_fp16.h>
#include <mma.h>
#include <math.h>
#include <stdint.h>

using namespace nvcuda;

#define TT 256      // timesteps
#define BB 256      // batch
#define DD 1024     // hidden dim
#define WS 2048     // W row stride (W is (D, 2D) row-major)

// fp16 shadow of the hidden state, written each step; A-operand source.
__device__ __align__(16) __half g_h[BB * DD];   // 512 KB

// ===========================================================================
// Kernel 1: preactivations, fp16 wmma (fp32 accum), 128x128 tile.
//   out[(b*TT + t)*DD + d] = bias[d] + sum_k x[(t*BB+b)*DD + k] * W[d*WS + k]
// ===========================================================================
#define X_BM 128
#define X_BN 128
#define X_BK 32
#define X_LDH 40                          // smem ldm in halfs (80B rows)
#define X_TILEH (X_BM * X_LDH)            // 5120 halfs = 10240 B
#define X_SMEM_BYTES 65536                // max(4 tiles = 40960, sC = 65536)

__global__ void __launch_bounds__(256)
gemm_x_f16(const float* __restrict__ x, const float* __restrict__ W,
           const float* __restrict__ bias, float* __restrict__ out)
{
    extern __shared__ char smraw[];
    __half* sA[2] = { (__half*)smraw,                 (__half*)(smraw + 2 * X_TILEH * 2) };
    __half* sB[2] = { (__half*)(smraw + X_TILEH * 2), (__half*)(smraw + 3 * X_TILEH * 2) };

    const int r0  = blockIdx.y * X_BM;    // row tile in (t*BB + b) space
    const int d0  = blockIdx.x * X_BN;
    const int tid = threadIdx.x;
    const int wid = tid >> 5;
    const int warpM = wid & 3;            // 4 x 32 rows
    const int warpN = wid >> 2;           // 2 x 64 cols

    wmma::fragment<wmma::accumulator, 16, 16, 16, float> acc[2][4];
    #pragma unroll
    for (int mi = 0; mi < 2; ++mi)
        #pragma unroll
        for (int ni = 0; ni < 4; ++ni)
            wmma::fill_fragment(acc[mi][ni], 0.0f);

    auto load_chunk = [&](int k0, __half* dA, __half* dB) {
        #pragma unroll
        for (int j = 0; j < 4; ++j) {
            int f   = tid + j * 256;      // 1024 float4
            int row = f >> 3;             // 8 float4 per row (32 floats)
            int c4  = f & 7;
            float4 va = *reinterpret_cast<const float4*>(
                &x[(size_t)(r0 + row) * DD + k0 + c4 * 4]);
            __half2* pa = reinterpret_cast<__half2*>(&dA[row * X_LDH + c4 * 4]);
            pa[0] = __floats2half2_rn(va.x, va.y);
            pa[1] = __floats2half2_rn(va.z, va.w);
            float4 vb = *reinterpret_cast<const float4*>(
                &W[(size_t)(d0 + row) * WS + k0 + c4 * 4]);
            __half2* pb = reinterpret_cast<__half2*>(&dB[row * X_LDH + c4 * 4]);
            pb[0] = __floats2half2_rn(vb.x, vb.y);
            pb[1] = __floats2half2_rn(vb.z, vb.w);
        }
    };

    load_chunk(0, sA[0], sB[0]);
    __syncthreads();

    const int NCH = DD / X_BK;            // 32 chunks
    for (int c = 0; c < NCH; ++c) {
        int cur = c & 1;
        if (c + 1 < NCH) load_chunk((c + 1) * X_BK, sA[cur ^ 1], sB[cur ^ 1]);

        #pragma unroll
        for (int kk = 0; kk < X_BK; kk += 16) {
            wmma::fragment<wmma::matrix_a, 16, 16, 16, __half, wmma::row_major> a[2];
            #pragma unroll
            for (int mi = 0; mi < 2; ++mi)
                wmma::load_matrix_sync(a[mi], &sA[cur][(warpM * 32 + mi * 16) * X_LDH + kk], X_LDH);
            #pragma unroll
            for (int ni = 0; ni < 4; ++ni) {
                wmma::fragment<wmma::matrix_b, 16, 16, 16, __half, wmma::col_major> b;
                wmma::load_matrix_sync(b, &sB[cur][(warpN * 64 + ni * 16) * X_LDH + kk], X_LDH);
                #pragma unroll
                for (int mi = 0; mi < 2; ++mi)
                    wmma::mma_sync(acc[mi][ni], a[mi], b, acc[mi][ni]);
            }
        }
        __syncthreads();
    }

    // Stage C (fp32) in smem, overlaying the fp16 tiles
    float* sC = (float*)smraw;
    #pragma unroll
    for (int mi = 0; mi < 2; ++mi)
        #pragma unroll
        for (int ni = 0; ni < 4; ++ni)
            wmma::store_matrix_sync(&sC[(warpM * 32 + mi * 16) * X_BN + warpN * 64 + ni * 16],
                                    acc[mi][ni], X_BN, wmma::mem_row_major);
    __syncthreads();

    // Epilogue: +bias, scatter. Block spans 128 rows => t constant.
    const int t = r0 >> 8;
    const int bbase = r0 & 255;
    #pragma unroll
    for (int j = 0; j < 16; ++j) {
        int f   = tid + j * 256;          // 4096 float4
        int row = f >> 5;                 // 32 float4 per row
        int c4  = f & 31;
        float4 bv = *reinterpret_cast<const float4*>(&bias[d0 + c4 * 4]);
        const float* cp = &sC[row * X_BN + c4 * 4];
        float4 o;
        o.x = cp[0] + bv.x; o.y = cp[1] + bv.y; o.z = cp[2] + bv.z; o.w = cp[3] + bv.w;
        *reinterpret_cast<float4*>(
            &out[((size_t)((bbase + row) * TT + t)) * DD + d0 + c4 * 4]) = o;
    }
}

// ===========================================================================
// Kernel 2: persistent recurrence, fp16 operands, fp32 accum.
//   - 128 blocks x 512 threads; block tile = 32 batch x 64 d.
//   - Wh stripe (64 x 1024 fp16 = 129 KB) resident in smem for all steps.
//   - h read as fp16 from g_h shadow via cp.async (16B), double-buffered.
//   - 16 warps = 2(M) x 4(N) x 2(K-half); combine via smem C0/C1.
//   - 8 independent batch groups of 16 blocks; acq/rel barrier.
// ===========================================================================
#define RH_BM 32
#define RH_BN 64
#define RH_BK 128
#define RH_NCH (DD / RH_BK)               // 8 chunks
#define RH_WLDH 1032                      // Wh ldm in halfs (1024+8)
#define RH_ALDH 136                       // h  ldm in halfs (128+8)
#define RH_GRPBLK 16                      // blocks per barrier group

#define RH_WH_BYTES (RH_BN * RH_WLDH * 2)             // 132096
#define RH_A_BYTES  (RH_BM * RH_ALDH * 2)             // 8704
#define RH_C_BYTES  (RH_BM * RH_BN * 4)               // 8192
#define RH_OFF_A0 RH_WH_BYTES                         // 132096
#define RH_OFF_A1 (RH_OFF_A0 + RH_A_BYTES)            // 140800
#define RH_OFF_C0 (RH_OFF_A1 + RH_A_BYTES)            // 149504
#define RH_OFF_C1 (RH_OFF_C0 + RH_C_BYTES)            // 157696
#define RH_SMEM_BYTES (RH_OFF_C1 + RH_C_BYTES)        // 165888

__device__ __align__(256) unsigned g_cnt[8 * 64];
__device__ __align__(256) unsigned g_phase[8 * 64];   // monotonic across replays

__device__ __forceinline__ unsigned bar_arrive_acqrel(unsigned* p) {
    unsigned old;
    asm volatile("atom.acq_rel.gpu.add.u32 %0,[%1],1;"
                 : "=r"(old) : "l"(p) : "memory");
    return old;
}
__device__ __forceinline__ void bar_reset_relaxed(unsigned* p) {
    asm volatile("st.relaxed.gpu.u32 [%0],0;" :: "l"(p) : "memory");
}
__device__ __forceinline__ void bar_release(unsigned* p) {
    asm volatile("red.release.gpu.add.u32 [%0],1;" :: "l"(p) : "memory");
}
__device__ __forceinline__ unsigned bar_poll_acquire(const unsigned* p) {
    unsigned v;
    asm volatile("ld.acquire.gpu.u32 %0,[%1];" : "=r"(v) : "l"(p) : "memory");
    return v;
}
__device__ __forceinline__ void cp16(uint32_t saddr, const void* gptr) {
    asm volatile("cp.async.cg.shared.global [%0], [%1], 16;"
                 :: "r"(saddr), "l"(gptr));
}

__global__ void __launch_bounds__(512)
rnn_persistent(const float* __restrict__ W, float* __restrict__ out)
{
    extern __shared__ char smraw[];
    __half* sWh   = (__half*)smraw;
    __half* sA[2] = { (__half*)(smraw + RH_OFF_A0), (__half*)(smraw + RH_OFF_A1) };
    float*  sC[2] = { (float*)(smraw + RH_OFF_C0),  (float*)(smraw + RH_OFF_C1) };
    __shared__ unsigned s_base;

    const int tid = threadIdx.x;
    const int wid = tid >> 5;             // 16 warps
    const int wM    = wid & 1;            // 2 x 16 rows = 32
    const int wN    = (wid >> 1) & 3;     // 4 x 16 cols = 64
    const int kHalf = wid >> 3;           // 2-way K split within 128 chunk

    const int nT = blockIdx.x & 15;       // 16 d-stripes of 64
    const int mT = blockIdx.x >> 4;       // 8 batch groups of 32 (barrier scope)
    const int d0 = nT * RH_BN;
    const int b0 = mT * RH_BM;

    unsigned* cntp   = &g_cnt[mT * 64];
    unsigned* phasep = &g_phase[mT * 64];

    const uint32_t sA_u32[2] = {
        (uint32_t)__cvta_generic_to_shared(sA[0]),
        (uint32_t)__cvta_generic_to_shared(sA[1])
    };

    // --- Load Wh stripe once (fp32 -> fp16 RN): sWh[d][k], d = 0..63 ---
    {
        const float* Wh = W + DD;
        #pragma unroll
        for (int j = 0; j < 32; ++j) {
            int f   = tid + j * 512;      // 16384 float4
            int row = f >> 8;             // 256 float4 per row
            int c4  = f & 255;
            float4 v = *reinterpret_cast<const float4*>(
                &Wh[(size_t)(d0 + row) * WS + c4 * 4]);
            __half2* p = reinterpret_cast<__half2*>(&sWh[row * RH_WLDH + c4 * 4]);
            p[0] = __floats2half2_rn(v.x, v.y);
            p[1] = __floats2half2_rn(v.z, v.w);
        }
    }

    if (tid == 0) s_base = bar_poll_acquire(phasep);
    __syncthreads();
    const unsigned base = s_base;

    // one 32x128 fp16 h chunk = 8192 B = 512 x 16B, 1 cp per thread
    auto issue_chunk = [&](int c, int buf) {
        int row = tid >> 4;               // 16 segs per row
        int sg  = tid & 15;
        const void* g = &g_h[(size_t)(b0 + row) * DD + c * RH_BK + sg * 8];
        uint32_t s = sA_u32[buf] + (uint32_t)(row * RH_ALDH + sg * 8) * 2u;
        cp16(s, g);
        asm volatile("cp.async.commit_group;");
    };

    // epilogue map: 32x64 floats = 512 float4, 1 per thread
    const int erow = tid >> 4;            // 16 float4 per row
    const int ec4  = tid & 15;

    for (int t = 0; t < TT; ++t) {
        if (t == 0) {
            float* p = &out[((size_t)((b0 + erow) * TT + 0)) * DD + d0 + ec4 * 4];
            float4 v = __ldcg(reinterpret_cast<const float4*>(p));
            v.x = tanhf(v.x); v.y = tanhf(v.y); v.z = tanhf(v.z); v.w = tanhf(v.w);
            *reinterpret_cast<float4*>(p) = v;
            __half2* hp = reinterpret_cast<__half2*>(
                &g_h[(size_t)(b0 + erow) * DD + d0 + ec4 * 4]);
            hp[0] = __floats2half2_rn(v.x, v.y);
            hp[1] = __floats2half2_rn(v.z, v.w);
        } else {
            // prefetch preactivation (independent of h)
            float* eptr = &out[((size_t)((b0 + erow) * TT + t)) * DD + d0 + ec4 * 4];
            float4 pre = __ldcg(reinterpret_cast<const float4*>(eptr));

            wmma::fragment<wmma::accumulator, 16, 16, 16, float> acc[2];
            wmma::fill_fragment(acc[0], 0.0f);
            wmma::fill_fragment(acc[1], 0.0f);

            issue_chunk(0, 0);
            issue_chunk(1, 1);

            for (int c = 0; c < RH_NCH; ++c) {       // 8 chunks
                int buf = c & 1;
                if (c == RH_NCH - 1) asm volatile("cp.async.wait_group 0;");
                else                 asm volatile("cp.async.wait_group 1;");
                __syncthreads();

                const __half* ap = &sA[buf][wM * 16 * RH_ALDH + kHalf * 64];
                const __half* bp = &sWh[(wN * 16) * RH_WLDH + c * RH_BK + kHalf * 64];
                #pragma unroll
                for (int kk = 0; kk < 64; kk += 16) {
                    wmma::fragment<wmma::matrix_a, 16, 16, 16, __half, wmma::row_major> a;
                    wmma::fragment<wmma::matrix_b, 16, 16, 16, __half, wmma::col_major> b;
                    wmma::load_matrix_sync(a, ap + kk, RH_ALDH);
                    wmma::load_matrix_sync(b, bp + kk, RH_WLDH);
                    wmma::mma_sync(acc[(kk >> 4) & 1], a, b, acc[(kk >> 4) & 1]);
                }
                __syncthreads();                     // reads of buf done
                if (c + 2 < RH_NCH) issue_chunk(c + 2, buf);
            }

            // reduce 2 accs within warp, combine kHalf warps via smem
            #pragma unroll
            for (int e = 0; e < acc[0].num_elements; ++e)
                acc[0].x[e] += acc[1].x[e];
            wmma::store_matrix_sync(&sC[kHalf][(wM * 16) * RH_BN + wN * 16],
                                    acc[0], RH_BN, wmma::mem_row_major);
            __syncthreads();

            // epilogue: sC0 + sC1 + preact -> tanh -> out (fp32) + g_h (fp16)
            {
                const float* c0 = &sC[0][erow * RH_BN + ec4 * 4];
                const float* c1 = &sC[1][erow * RH_BN + ec4 * 4];
                float4 o;
                o.x = tanhf(pre.x + c0[0] + c1[0]);
                o.y = tanhf(pre.y + c0[1] + c1[1]);
                o.z = tanhf(pre.z + c0[2] + c1[2]);
                o.w = tanhf(pre.w + c0[3] + c1[3]);
                *reinterpret_cast<float4*>(eptr) = o;
                __half2* hp = reinterpret_cast<__half2*>(
                    &g_h[(size_t)(b0 + erow) * DD + d0 + ec4 * 4]);
                hp[0] = __floats2half2_rn(o.x, o.y);
                hp[1] = __floats2half2_rn(o.z, o.w);
            }
        }

        // group barrier (16 blocks sharing this batch group), skip after last
        if (t != TT - 1) {
            __syncthreads();
            if (tid == 0) {
                unsigned old = bar_arrive_acqrel(cntp);
                if (old == RH_GRPBLK - 1) {
                    bar_reset_relaxed(cntp);
                    bar_release(phasep);
                } else {
                    const unsigned target = base + (unsigned)(t + 1);
                    while ((int)(bar_poll_acquire(phasep) - target) < 0) { }
                }
            }
            __syncthreads();
        }
    }
}

// ===========================================================================
// Launch
// ===========================================================================
extern "C" void kernel_launch(void* const* d_in, const int* in_sizes, int n_in,
                              void* d_out, int out_size)
{
    const float* x    = (const float*)d_in[0];
    const float* W    = (const float*)d_in[1];
    const float* bias = (const float*)d_in[2];
    float* out = (float*)d_out;

    cudaFuncSetAttribute(gemm_x_f16, cudaFuncAttributeMaxDynamicSharedMemorySize,
                         X_SMEM_BYTES);
    cudaFuncSetAttribute(rnn_persistent, cudaFuncAttributeMaxDynamicSharedMemorySize,
                         RH_SMEM_BYTES);

    dim3 g1(DD / X_BN, (TT * BB) / X_BM);   // (8, 512)
    gemm_x_f16<<<g1, 256, X_SMEM_BYTES>>>(x, W, bias, out);

    rnn_persistent<<<128, 512, RH_SMEM_BYTES>>>(W, out);
}